// round 16
// baseline (speedup 1.0000x reference)
#include <cuda_runtime.h>
#include <math.h>
#include <cstdint>

// ---------------- problem constants ----------------
#define BATCH   32
#define LSEQ    16
#define BL      512
#define M1      25088        // BL * 49
#define C1      576
#define DCNN    64
#define DRNN    256
#define G3      768
#define HORIZON 10

#define KC      6912         // fused conv K = 3*48*48
#define KSPLIT  6
#define KPER    1152         // KC / KSPLIT
#define NCH     72           // KPER / 16
#define FPAD    62208        // 3*144*144
#define FPLANE  20736        // 144*144

// front_kernel block ranges
#define WCBLK   108          // 12 x 9
#define PREPBLK 1152
#define PADBLK  31104        // 512*FPAD/4/256
#define FRONTBLK (WCBLK + PREPBLK + PADBLK)

// ---------------- scratch (device globals) ----------------
__device__ float g_fpad[(size_t)BL * FPAD];
__device__ float g_wcT[KC * DCNN];
__device__ float g_t[DCNN * 9];
__device__ float g_yp[(size_t)KSPLIT * M1 * DCNN];
__device__ float g_s[BL * DRNN];
__device__ float g_gi[BL * G3];
__device__ float g_wihp[G3 * DRNN];   // [kq][gate][d][4]
__device__ float g_whhp[G3 * DRNN];
__device__ float g_fitp[DRNN * DRNN]; // [kq][d][4]
__device__ float g_h[BATCH * DRNN];

// =====================================================================
// front_kernel: wc_gemm (108 blocks) | prep (1152 blocks) | pad (31104)
// =====================================================================
__global__ __launch_bounds__(256) void front_kernel(
    const float* __restrict__ frames,
    const float* __restrict__ cnn_w,
    const float* __restrict__ cnn1_w,
    const float* __restrict__ b1,
    const float* __restrict__ w_ih,
    const float* __restrict__ w_hh,
    const float* __restrict__ fi_w)
{
    int bid = blockIdx.x;
    int tid = threadIdx.x;

    if (bid < WCBLK) {
        __shared__ float As[16][68];
        __shared__ float Bs[16][68];
        int jt = bid % 12, tap = bid / 12;
        int ty16 = tap / 3, tx16 = tap - ty16 * 3;
        int tx = tid & 15, ty = tid >> 4;

        float acc[4][4];
#pragma unroll
        for (int i = 0; i < 4; i++)
#pragma unroll
            for (int j = 0; j < 4; j++) acc[i][j] = 0.f;

        int kkB = tid >> 4, j4 = (tid & 15) * 4;
        for (int mc0 = 0; mc0 < C1; mc0 += 16) {
#pragma unroll
            for (int e = 0; e < 4; e++) {
                int u = tid + e * 256;
                int oc = u >> 4, kk = u & 15;
                As[kk][oc] = cnn1_w[oc * 5184 + (mc0 + kk) * 9 + tap];
            }
            *(float4*)&Bs[kkB][j4] = *(const float4*)(cnn_w + (mc0 + kkB) * 768 + jt * 64 + j4);
            __syncthreads();
#pragma unroll
            for (int kk = 0; kk < 16; kk++) {
                float a[4], b[4];
#pragma unroll
                for (int i = 0; i < 4; i++) a[i] = As[kk][ty * 4 + i];
#pragma unroll
                for (int j = 0; j < 4; j++) b[j] = Bs[kk][tx * 4 + j];
#pragma unroll
                for (int i = 0; i < 4; i++)
#pragma unroll
                    for (int j = 0; j < 4; j++) acc[i][j] += a[i] * b[j];
            }
            __syncthreads();
        }

#pragma unroll
        for (int i = 0; i < 4; i++) {
            int oc = ty * 4 + i;
#pragma unroll
            for (int jj = 0; jj < 4; jj++) {
                int j = jt * 64 + tx * 4 + jj;
                int c = j >> 8, rem = j & 255;
                int iy = rem >> 4, ix = rem & 15;
                int k = c * 2304 + (ty16 * 16 + iy) * 48 + tx16 * 16 + ix;
                g_wcT[k * DCNN + oc] = acc[i][jj];
            }
        }
    } else if (bid < WCBLK + PREPBLK) {
        int i = (bid - WCBLK) * 256 + tid;
        if (i < G3 * DRNN) {
            int row = i >> 8;
            int k   = i & 255;
            int g = row >> 8, d = row & 255;
            int kq = k >> 2, j = k & 3;
            int dst = ((kq * 3 + g) * DRNN + d) * 4 + j;
            g_wihp[dst] = w_ih[i];
            g_whhp[dst] = w_hh[i];
        }
        if (i < DRNN * DRNN) {
            int d = i >> 8, k = i & 255;
            int kq = k >> 2, j = k & 3;
            g_fitp[(kq * DRNN + d) * 4 + j] = fi_w[i];
        }
        if (i < DCNN * 9) {
            int oc = i / 9, tap = i - oc * 9;
            float s = 0.f;
#pragma unroll 4
            for (int mc = 0; mc < C1; mc++)
                s += cnn1_w[oc * 5184 + mc * 9 + tap] * b1[mc];
            g_t[i] = s;
        }
    } else {
        int u = (bid - WCBLK - PREPBLK) * 256 + tid;
        int n = u / 15552;
        int rem = u - n * 15552;
        int c = rem / 5184;
        int rem2 = rem - c * 5184;
        int y = rem2 / 36;
        int x4 = (rem2 - y * 36) * 4;

        float4 v = make_float4(0.f, 0.f, 0.f, 0.f);
        if (y >= 16 && y < 128 && x4 >= 16 && x4 < 128)
            v = *(const float4*)(frames + n * 37632 + c * 12544 + (y - 16) * 112 + (x4 - 16));
        *(float4*)(g_fpad + (size_t)n * FPAD + c * FPLANE + y * 144 + x4) = v;
    }
}

// =====================================================================
// fused conv GEMM: R12 structure + forced 3 CTAs/SM
// =====================================================================
__global__ __launch_bounds__(256, 3) void fused_gemm(void)
{
    __shared__ __align__(16) float As[2][16][132];
    __shared__ __align__(16) float Bs[2][16][68];

    int tid = threadIdx.x;
    int tx = tid & 15, ty = tid >> 4;
    int rowBase = blockIdx.x * 128;
    int ks = blockIdx.y;
    int kbase = ks * KPER;

    int abase[2], arow[2], aq4[2];
#pragma unroll
    for (int e = 0; e < 2; e++) {
        int idx = tid + e * 256;
        int row = idx >> 2, q4 = idx & 3;
        int m = rowBase + row;
        int n = m / 49, p = m - n * 49;
        int py = p / 7, px = p - py * 7;
        abase[e] = n * FPAD + (py * 16) * 144 + px * 16;
        arow[e] = row;
        aq4[e] = q4;
    }
    int kkB = tid >> 4, j4 = (tid & 15) * 4;

    float acc[8][4];
#pragma unroll
    for (int i = 0; i < 8; i++)
#pragma unroll
        for (int j = 0; j < 4; j++) acc[i][j] = 0.f;

    auto chunk_off = [&](int ch) {
        int k0 = kbase + ch * 16;
        int c = k0 / 2304;
        int r = k0 - c * 2304;
        int wy = r / 48;
        int wx0 = r - wy * 48;
        return c * FPLANE + wy * 144 + wx0;
    };

    float4 ra[2], rb;
    auto stage = [&](int ch) {
        int off = chunk_off(ch);
#pragma unroll
        for (int e = 0; e < 2; e++)
            ra[e] = *(const float4*)(g_fpad + (size_t)abase[e] + off + aq4[e] * 4);
        rb = *(const float4*)(g_wcT + (size_t)(kbase + ch * 16 + kkB) * DCNN + j4);
    };
    auto commit = [&](int buf) {
#pragma unroll
        for (int e = 0; e < 2; e++) {
            int b0 = aq4[e] * 4, r = arow[e];
            As[buf][b0 + 0][r] = ra[e].x;
            As[buf][b0 + 1][r] = ra[e].y;
            As[buf][b0 + 2][r] = ra[e].z;
            As[buf][b0 + 3][r] = ra[e].w;
        }
        *(float4*)&Bs[buf][kkB][j4] = rb;
    };

    stage(0);
    commit(0);
    __syncthreads();
    stage(1);

    for (int ch = 0; ch < NCH; ch++) {
        int b = ch & 1;
#pragma unroll
        for (int kk = 0; kk < 16; kk++) {
            float4 a0 = *(const float4*)&As[b][kk][ty * 8];
            float4 a1 = *(const float4*)&As[b][kk][ty * 8 + 4];
            float4 b4 = *(const float4*)&Bs[b][kk][tx * 4];
            float av[8] = {a0.x, a0.y, a0.z, a0.w, a1.x, a1.y, a1.z, a1.w};
            float bv[4] = {b4.x, b4.y, b4.z, b4.w};
#pragma unroll
            for (int i = 0; i < 8; i++)
#pragma unroll
                for (int j = 0; j < 4; j++) acc[i][j] += av[i] * bv[j];
        }
        if (ch + 1 < NCH) commit(b ^ 1);
        __syncthreads();
        if (ch + 2 < NCH) stage(ch + 2);
    }

    float* outp = g_yp + (size_t)ks * M1 * DCNN;
#pragma unroll
    for (int i = 0; i < 8; i++) {
        int m = rowBase + ty * 8 + i;
        *(float4*)(outp + (size_t)m * DCNN + tx * 4) =
            make_float4(acc[i][0], acc[i][1], acc[i][2], acc[i][3]);
    }
}

// ---------------- fused pool + adapter (bias field inlined) ----------------
__global__ __launch_bounds__(256) void poolad_kernel(
    const float* __restrict__ x,
    const float* __restrict__ a0_w, const float* __restrict__ a0_b,
    const float* __restrict__ ai_w, const float* __restrict__ ai_b,
    const float* __restrict__ an_w, const float* __restrict__ an_b,
    const float* __restrict__ bn_g, const float* __restrict__ bn_b,
    const float* __restrict__ bn_m, const float* __restrict__ bn_v,
    const float* __restrict__ b2)
{
    __shared__ float part[4][DCNN];
    __shared__ float s0[16];
    __shared__ float cat[80];

    int r = blockIdx.x;
    int tid = threadIdx.x;
    int pg = tid >> 6;
    int oc = tid & 63;

    float tv[9];
#pragma unroll
    for (int q = 0; q < 9; q++) tv[q] = g_t[oc * 9 + q];
    float base2 = b2[oc];

    const float* p0 = g_yp + (size_t)r * 49 * DCNN + oc;
    const size_t str = (size_t)M1 * DCNN;
    float s = 0.f;
    for (int p = pg; p < 49; p += 4) {
        int py = p / 7, px = p - py * 7;
        float v = base2;
#pragma unroll
        for (int ty = 0; ty < 3; ty++)
#pragma unroll
            for (int tx = 0; tx < 3; tx++) {
                int ny = py + ty - 1, nx = px + tx - 1;
                if ((unsigned)ny < 7u && (unsigned)nx < 7u)
                    v += tv[ty * 3 + tx];
            }
#pragma unroll
        for (int q = 0; q < KSPLIT; q++) v += p0[q * str + p * DCNN];
        s += fmaxf(v, 0.f);
    }
    part[pg][oc] = s;
    __syncthreads();

    const float* xr = x + r * 12;
    if (tid < 64) {
        float t = part[0][tid] + part[1][tid] + part[2][tid] + part[3][tid];
        float inv = bn_g[tid] * rsqrtf(bn_v[tid] + 1e-5f);
        cat[16 + tid] = (t * (1.f / 49.f) - bn_m[tid]) * inv + bn_b[tid];
    } else if (tid < 80) {
        int j = tid - 64;
        float a = a0_b[j];
#pragma unroll
        for (int q = 0; q < 12; q++) a += xr[q] * a0_w[j * 12 + q];
        s0[j] = fmaxf(a, 0.f);
    }
    __syncthreads();

    if (tid < 16) {
        float a = ai_b[tid];
#pragma unroll
        for (int j = 0; j < 16; j++) a += s0[j] * ai_w[tid * 16 + j];
        cat[tid] = s0[tid] + fmaxf(a, 0.f);
    }
    __syncthreads();

    float a = an_b[tid];
#pragma unroll
    for (int j = 0; j < 80; j++) a += cat[j] * an_w[tid * 80 + j];
    g_s[r * DRNN + tid] = fmaxf(a, 0.f);
}

// ---------------- encoder input gates: 64 blocks x 8 rows, unrolled ------
__global__ __launch_bounds__(256) void gi_kernel(const float* __restrict__ b_ih)
{
    int blk = blockIdx.x;
    int d = threadIdx.x;
    __shared__ __align__(16) float svT[DRNN][8];

    for (int rr = 0; rr < 8; rr++) {
        int q = blk * 8 + rr;
        int t = q >> 5, b = q & 31;
        int r = b * 16 + t;
        svT[d][rr] = g_s[r * DRNN + d];
    }
    __syncthreads();

    float a0[8], a1[8], a2[8];
#pragma unroll
    for (int rr = 0; rr < 8; rr++) { a0[rr] = 0.f; a1[rr] = 0.f; a2[rr] = 0.f; }

    const float4* Wp = (const float4*)g_wihp;
#pragma unroll 4
    for (int kq = 0; kq < 64; kq++) {
        float4 w0 = Wp[(kq * 3 + 0) * DRNN + d];
        float4 w1 = Wp[(kq * 3 + 1) * DRNN + d];
        float4 w2 = Wp[(kq * 3 + 2) * DRNN + d];
        float w0a[4] = {w0.x, w0.y, w0.z, w0.w};
        float w1a[4] = {w1.x, w1.y, w1.z, w1.w};
        float w2a[4] = {w2.x, w2.y, w2.z, w2.w};
#pragma unroll
        for (int j = 0; j < 4; j++) {
            int k = kq * 4 + j;
            const float4* s4 = (const float4*)&svT[k][0];
#pragma unroll
            for (int c = 0; c < 2; c++) {
                float4 sv = s4[c];
                float s[4] = {sv.x, sv.y, sv.z, sv.w};
#pragma unroll
                for (int u = 0; u < 4; u++) {
                    int rr = c * 4 + u;
                    a0[rr] += s[u] * w0a[j];
                    a1[rr] += s[u] * w1a[j];
                    a2[rr] += s[u] * w2a[j];
                }
            }
        }
    }

    float bi0 = b_ih[d], bi1 = b_ih[256 + d], bi2 = b_ih[512 + d];
#pragma unroll
    for (int rr = 0; rr < 8; rr++) {
        float* o = g_gi + (size_t)(blk * 8 + rr) * G3;
        o[d] = a0[rr] + bi0;
        o[256 + d] = a1[rr] + bi1;
        o[512 + d] = a2[rr] + bi2;
    }
}

__device__ __forceinline__ float sigmoidf_(float v) { return 1.f / (1.f + expf(-v)); }

// ---------------- fused encoder: 512 threads, split-K ----------------
__global__ __launch_bounds__(512) void encoder_kernel(const float* __restrict__ b_hh)
{
    int b = blockIdx.x;
    int tid = threadIdx.x;
    int half = tid >> 8;
    int d = tid & 255;
    __shared__ __align__(16) float hs[DRNN];
    __shared__ float part[3][DRNN];

    if (half == 0) hs[d] = 0.f;
    __syncthreads();

    float bh0 = b_hh[d], bh1 = b_hh[256 + d], bh2 = b_hh[512 + d];
    const float4* Wp = (const float4*)g_whhp;
    int kq0 = half * 32;

    for (int t = 0; t < LSEQ; t++) {
        float a0 = 0.f, a1 = 0.f, a2 = 0.f;
#pragma unroll 4
        for (int kq = kq0; kq < kq0 + 32; kq++) {
            float4 h4 = *(const float4*)&hs[kq * 4];
            float4 w0 = Wp[(kq * 3 + 0) * DRNN + d];
            float4 w1 = Wp[(kq * 3 + 1) * DRNN + d];
            float4 w2 = Wp[(kq * 3 + 2) * DRNN + d];
            a0 += h4.x * w0.x + h4.y * w0.y + h4.z * w0.z + h4.w * w0.w;
            a1 += h4.x * w1.x + h4.y * w1.y + h4.z * w1.z + h4.w * w1.w;
            a2 += h4.x * w2.x + h4.y * w2.y + h4.z * w2.z + h4.w * w2.w;
        }
        if (half == 1) { part[0][d] = a0; part[1][d] = a1; part[2][d] = a2; }
        float oldh = hs[d];
        __syncthreads();
        if (half == 0) {
            a0 += part[0][d] + bh0;
            a1 += part[1][d] + bh1;
            a2 += part[2][d] + bh2;
            const float* gi = g_gi + (size_t)(t * 32 + b) * G3;
            float rr = sigmoidf_(gi[d] + a0);
            float zz = sigmoidf_(gi[256 + d] + a1);
            float nn = tanhf(gi[512 + d] + rr * a2);
            hs[d] = (1.f - zz) * nn + zz * oldh;
        }
        __syncthreads();
    }
    if (half == 0) g_h[b * DRNN + d] = hs[d];
}

// ---------------- fused decoder: 512 threads, split-K ----------------
__global__ __launch_bounds__(512) void decoder_kernel(
    const float* __restrict__ b_ih, const float* __restrict__ b_hh,
    const float* __restrict__ fi_b,
    const float* __restrict__ fn_w, const float* __restrict__ fn_b,
    float* __restrict__ out)
{
    int b = blockIdx.x;
    int tid = threadIdx.x;
    int half = tid >> 8;
    int d = tid & 255;
    __shared__ __align__(16) float hs[DRNN];
    __shared__ __align__(16) float xs[DRNN];
    __shared__ float xr[DRNN];
    __shared__ float part[6][DRNN];
    __shared__ float partf[DRNN];

    if (half == 0) {
        float h0 = g_h[b * DRNN + d];
        hs[d] = h0;
        xs[d] = h0;
    }
    __syncthreads();

    float bh0 = b_hh[d], bh1 = b_hh[256 + d], bh2 = b_hh[512 + d];
    float bi0 = b_ih[d], bi1 = b_ih[256 + d], bi2 = b_ih[512 + d];
    float fib = fi_b[d];
    const float4* Wh = (const float4*)g_whhp;
    const float4* Wi = (const float4*)g_wihp;
    const float4* Wf = (const float4*)g_fitp;
    int kq0 = half * 32;

    for (int t = 0; t < HORIZON; t++) {
        float a0 = 0.f, a1 = 0.f, a2 = 0.f;
        float c0 = 0.f, c1 = 0.f, c2 = 0.f;
#pragma unroll 4
        for (int kq = kq0; kq < kq0 + 32; kq++) {
            float4 h4 = *(const float4*)&hs[kq * 4];
            float4 x4 = *(const float4*)&xs[kq * 4];
            float4 w0 = Wh[(kq * 3 + 0) * DRNN + d];
            float4 w1 = Wh[(kq * 3 + 1) * DRNN + d];
            float4 w2 = Wh[(kq * 3 + 2) * DRNN + d];
            float4 v0 = Wi[(kq * 3 + 0) * DRNN + d];
            float4 v1 = Wi[(kq * 3 + 1) * DRNN + d];
            float4 v2 = Wi[(kq * 3 + 2) * DRNN + d];
            a0 += h4.x * w0.x + h4.y * w0.y + h4.z * w0.z + h4.w * w0.w;
            a1 += h4.x * w1.x + h4.y * w1.y + h4.z * w1.z + h4.w * w1.w;
            a2 += h4.x * w2.x + h4.y * w2.y + h4.z * w2.z + h4.w * w2.w;
            c0 += x4.x * v0.x + x4.y * v0.y + x4.z * v0.z + x4.w * v0.w;
            c1 += x4.x * v1.x + x4.y * v1.y + x4.z * v1.z + x4.w * v1.w;
            c2 += x4.x * v2.x + x4.y * v2.y + x4.z * v2.z + x4.w * v2.w;
        }
        if (half == 1) {
            part[0][d] = a0; part[1][d] = a1; part[2][d] = a2;
            part[3][d] = c0; part[4][d] = c1; part[5][d] = c2;
        }
        float oldh = hs[d];
        __syncthreads();
        if (half == 0) {
            a0 += part[0][d] + bh0;
            a1 += part[1][d] + bh1;
            a2 += part[2][d] + bh2;
            c0 += part[3][d] + bi0;
            c1 += part[4][d] + bi1;
            c2 += part[5][d] + bi2;
            float rr = sigmoidf_(c0 + a0);
            float zz = sigmoidf_(c1 + a1);
            float nn = tanhf(c2 + rr * a2);
            hs[d] = (1.f - zz) * nn + zz * oldh;
        }
        __syncthreads();

        float a = 0.f;
#pragma unroll 4
        for (int kq = kq0; kq < kq0 + 32; kq++) {
            float4 h4 = *(const float4*)&hs[kq * 4];
            float4 wv = Wf[kq * DRNN + d];
            a += h4.x * wv.x + h4.y * wv.y + h4.z * wv.z + h4.w * wv.w;
        }
        if (half == 1) partf[d] = a;
        __syncthreads();
        if (half == 0) {
            a += partf[d] + fib;
            float v = hs[d] + fmaxf(a, 0.f);
            xr[d] = v;
            xs[d] = v;
        }
        __syncthreads();

        if (tid < 64) {
            int dd = tid >> 5, lane = tid & 31;
            float s = 0.f;
#pragma unroll
            for (int k = lane; k < DRNN; k += 32) s += xr[k] * fn_w[dd * DRNN + k];
#pragma unroll
            for (int o = 16; o > 0; o >>= 1)
                s += __shfl_down_sync(0xffffffffu, s, o);
            if (lane == 0)
                out[(t * 32 + b) * 2 + dd] = tanhf(s + fn_b[dd]);
        }
        __syncthreads();
    }
}

// ---------------- launch ----------------
extern "C" void kernel_launch(void* const* d_in, const int* in_sizes, int n_in,
                              void* d_out, int out_size)
{
    const float* x      = (const float*)d_in[0];
    const float* frames = (const float*)d_in[1];
    const float* cnn_w  = (const float*)d_in[2];
    const float* cnn_b  = (const float*)d_in[3];
    const float* cnn1_w = (const float*)d_in[4];
    const float* cnn1_b = (const float*)d_in[5];
    const float* bn_g   = (const float*)d_in[6];
    const float* bn_b   = (const float*)d_in[7];
    const float* bn_m   = (const float*)d_in[8];
    const float* bn_v   = (const float*)d_in[9];
    const float* a0_w   = (const float*)d_in[10];
    const float* a0_b   = (const float*)d_in[11];
    const float* ai_w   = (const float*)d_in[12];
    const float* ai_b   = (const float*)d_in[13];
    const float* an_w   = (const float*)d_in[14];
    const float* an_b   = (const float*)d_in[15];
    const float* w_ih   = (const float*)d_in[16];
    const float* w_hh   = (const float*)d_in[17];
    const float* b_ih   = (const float*)d_in[18];
    const float* b_hh   = (const float*)d_in[19];
    const float* fi_w   = (const float*)d_in[20];
    const float* fi_b   = (const float*)d_in[21];
    const float* fn_w   = (const float*)d_in[22];
    const float* fn_b   = (const float*)d_in[23];
    float* out = (float*)d_out;

    front_kernel<<<FRONTBLK, 256>>>(frames, cnn_w, cnn1_w, cnn_b,
                                    w_ih, w_hh, fi_w);

    dim3 gg(M1 / 128, KSPLIT);
    fused_gemm<<<gg, 256>>>();

    poolad_kernel<<<BL, 256>>>(x, a0_w, a0_b, ai_w, ai_b, an_w, an_b,
                               bn_g, bn_b, bn_m, bn_v, cnn1_b);
    gi_kernel<<<64, DRNN>>>(b_ih);

    encoder_kernel<<<BATCH, 512>>>(b_hh);
    decoder_kernel<<<BATCH, 512>>>(b_ih, b_hh, fi_b, fn_w, fn_b, out);
}

// round 17
// speedup vs baseline: 1.0293x; 1.0293x over previous
#include <cuda_runtime.h>
#include <math.h>
#include <cstdint>

// ---------------- problem constants ----------------
#define BATCH   32
#define LSEQ    16
#define BL      512
#define M1      25088        // BL * 49
#define C1      576
#define DCNN    64
#define DRNN    256
#define G3      768
#define HORIZON 10

#define KC      6912         // fused conv K = 3*48*48
#define KSPLIT  6
#define KPER    1152         // KC / KSPLIT
#define NCH     72           // KPER / 16
#define FPAD    62208        // 3*144*144
#define FPLANE  20736        // 144*144

// front_kernel block ranges
#define WCBLK   108          // 12 x 9
#define PREPBLK 1152
#define PADBLK  31104        // 512*FPAD/4/256
#define FRONTBLK (WCBLK + PREPBLK + PADBLK)

// ---------------- scratch (device globals) ----------------
__device__ float g_fpad[(size_t)BL * FPAD];
__device__ float g_wcT[KC * DCNN];
__device__ float g_t[DCNN * 9];
__device__ float g_yp[(size_t)KSPLIT * M1 * DCNN];
__device__ float g_s[BL * DRNN];
__device__ float g_gi[BL * G3];
__device__ float g_wihp[G3 * DRNN];   // [kq][gate][d][4]
__device__ float g_whhp[G3 * DRNN];
__device__ float g_fitp[DRNN * DRNN]; // [kq][d][4]
__device__ float g_h[BATCH * DRNN];

// =====================================================================
// front_kernel: wc_gemm (108 blocks) | prep (1152 blocks) | pad (31104)
// =====================================================================
__global__ __launch_bounds__(256) void front_kernel(
    const float* __restrict__ frames,
    const float* __restrict__ cnn_w,
    const float* __restrict__ cnn1_w,
    const float* __restrict__ b1,
    const float* __restrict__ w_ih,
    const float* __restrict__ w_hh,
    const float* __restrict__ fi_w)
{
    int bid = blockIdx.x;
    int tid = threadIdx.x;

    if (bid < WCBLK) {
        __shared__ float As[16][68];
        __shared__ float Bs[16][68];
        int jt = bid % 12, tap = bid / 12;
        int ty16 = tap / 3, tx16 = tap - ty16 * 3;
        int tx = tid & 15, ty = tid >> 4;

        float acc[4][4];
#pragma unroll
        for (int i = 0; i < 4; i++)
#pragma unroll
            for (int j = 0; j < 4; j++) acc[i][j] = 0.f;

        int kkB = tid >> 4, j4 = (tid & 15) * 4;
        for (int mc0 = 0; mc0 < C1; mc0 += 16) {
#pragma unroll
            for (int e = 0; e < 4; e++) {
                int u = tid + e * 256;
                int oc = u >> 4, kk = u & 15;
                As[kk][oc] = cnn1_w[oc * 5184 + (mc0 + kk) * 9 + tap];
            }
            *(float4*)&Bs[kkB][j4] = *(const float4*)(cnn_w + (mc0 + kkB) * 768 + jt * 64 + j4);
            __syncthreads();
#pragma unroll
            for (int kk = 0; kk < 16; kk++) {
                float a[4], b[4];
#pragma unroll
                for (int i = 0; i < 4; i++) a[i] = As[kk][ty * 4 + i];
#pragma unroll
                for (int j = 0; j < 4; j++) b[j] = Bs[kk][tx * 4 + j];
#pragma unroll
                for (int i = 0; i < 4; i++)
#pragma unroll
                    for (int j = 0; j < 4; j++) acc[i][j] += a[i] * b[j];
            }
            __syncthreads();
        }

#pragma unroll
        for (int i = 0; i < 4; i++) {
            int oc = ty * 4 + i;
#pragma unroll
            for (int jj = 0; jj < 4; jj++) {
                int j = jt * 64 + tx * 4 + jj;
                int c = j >> 8, rem = j & 255;
                int iy = rem >> 4, ix = rem & 15;
                int k = c * 2304 + (ty16 * 16 + iy) * 48 + tx16 * 16 + ix;
                g_wcT[k * DCNN + oc] = acc[i][jj];
            }
        }
    } else if (bid < WCBLK + PREPBLK) {
        int i = (bid - WCBLK) * 256 + tid;
        if (i < G3 * DRNN) {
            int row = i >> 8;
            int k   = i & 255;
            int g = row >> 8, d = row & 255;
            int kq = k >> 2, j = k & 3;
            int dst = ((kq * 3 + g) * DRNN + d) * 4 + j;
            g_wihp[dst] = w_ih[i];
            g_whhp[dst] = w_hh[i];
        }
        if (i < DRNN * DRNN) {
            int d = i >> 8, k = i & 255;
            int kq = k >> 2, j = k & 3;
            g_fitp[(kq * DRNN + d) * 4 + j] = fi_w[i];
        }
        if (i < DCNN * 9) {
            int oc = i / 9, tap = i - oc * 9;
            float s = 0.f;
#pragma unroll 4
            for (int mc = 0; mc < C1; mc++)
                s += cnn1_w[oc * 5184 + mc * 9 + tap] * b1[mc];
            g_t[i] = s;
        }
    } else {
        int u = (bid - WCBLK - PREPBLK) * 256 + tid;
        int n = u / 15552;
        int rem = u - n * 15552;
        int c = rem / 5184;
        int rem2 = rem - c * 5184;
        int y = rem2 / 36;
        int x4 = (rem2 - y * 36) * 4;

        float4 v = make_float4(0.f, 0.f, 0.f, 0.f);
        if (y >= 16 && y < 128 && x4 >= 16 && x4 < 128)
            v = *(const float4*)(frames + n * 37632 + c * 12544 + (y - 16) * 112 + (x4 - 16));
        *(float4*)(g_fpad + (size_t)n * FPAD + c * FPLANE + y * 144 + x4) = v;
    }
}

// =====================================================================
// fused conv GEMM (EXACT R12-measured-good: no minBlocks attribute)
// =====================================================================
__global__ __launch_bounds__(256) void fused_gemm(void)
{
    __shared__ __align__(16) float As[2][16][132];
    __shared__ __align__(16) float Bs[2][16][68];

    int tid = threadIdx.x;
    int tx = tid & 15, ty = tid >> 4;
    int rowBase = blockIdx.x * 128;
    int ks = blockIdx.y;
    int kbase = ks * KPER;

    int abase[2], arow[2], aq4[2];
#pragma unroll
    for (int e = 0; e < 2; e++) {
        int idx = tid + e * 256;
        int row = idx >> 2, q4 = idx & 3;
        int m = rowBase + row;
        int n = m / 49, p = m - n * 49;
        int py = p / 7, px = p - py * 7;
        abase[e] = n * FPAD + (py * 16) * 144 + px * 16;
        arow[e] = row;
        aq4[e] = q4;
    }
    int kkB = tid >> 4, j4 = (tid & 15) * 4;

    float acc[8][4];
#pragma unroll
    for (int i = 0; i < 8; i++)
#pragma unroll
        for (int j = 0; j < 4; j++) acc[i][j] = 0.f;

    auto chunk_off = [&](int ch) {
        int k0 = kbase + ch * 16;
        int c = k0 / 2304;
        int r = k0 - c * 2304;
        int wy = r / 48;
        int wx0 = r - wy * 48;
        return c * FPLANE + wy * 144 + wx0;
    };

    float4 ra[2], rb;
    auto stage = [&](int ch) {
        int off = chunk_off(ch);
#pragma unroll
        for (int e = 0; e < 2; e++)
            ra[e] = *(const float4*)(g_fpad + (size_t)abase[e] + off + aq4[e] * 4);
        rb = *(const float4*)(g_wcT + (size_t)(kbase + ch * 16 + kkB) * DCNN + j4);
    };
    auto commit = [&](int buf) {
#pragma unroll
        for (int e = 0; e < 2; e++) {
            int b0 = aq4[e] * 4, r = arow[e];
            As[buf][b0 + 0][r] = ra[e].x;
            As[buf][b0 + 1][r] = ra[e].y;
            As[buf][b0 + 2][r] = ra[e].z;
            As[buf][b0 + 3][r] = ra[e].w;
        }
        *(float4*)&Bs[buf][kkB][j4] = rb;
    };

    stage(0);
    commit(0);
    __syncthreads();
    stage(1);

    for (int ch = 0; ch < NCH; ch++) {
        int b = ch & 1;
#pragma unroll
        for (int kk = 0; kk < 16; kk++) {
            float4 a0 = *(const float4*)&As[b][kk][ty * 8];
            float4 a1 = *(const float4*)&As[b][kk][ty * 8 + 4];
            float4 b4 = *(const float4*)&Bs[b][kk][tx * 4];
            float av[8] = {a0.x, a0.y, a0.z, a0.w, a1.x, a1.y, a1.z, a1.w};
            float bv[4] = {b4.x, b4.y, b4.z, b4.w};
#pragma unroll
            for (int i = 0; i < 8; i++)
#pragma unroll
                for (int j = 0; j < 4; j++) acc[i][j] += av[i] * bv[j];
        }
        if (ch + 1 < NCH) commit(b ^ 1);
        __syncthreads();
        if (ch + 2 < NCH) stage(ch + 2);
    }

    float* outp = g_yp + (size_t)ks * M1 * DCNN;
#pragma unroll
    for (int i = 0; i < 8; i++) {
        int m = rowBase + ty * 8 + i;
        *(float4*)(outp + (size_t)m * DCNN + tx * 4) =
            make_float4(acc[i][0], acc[i][1], acc[i][2], acc[i][3]);
    }
}

// ---------------- fused pool + adapter (bias field inlined) ----------------
__global__ __launch_bounds__(256) void poolad_kernel(
    const float* __restrict__ x,
    const float* __restrict__ a0_w, const float* __restrict__ a0_b,
    const float* __restrict__ ai_w, const float* __restrict__ ai_b,
    const float* __restrict__ an_w, const float* __restrict__ an_b,
    const float* __restrict__ bn_g, const float* __restrict__ bn_b,
    const float* __restrict__ bn_m, const float* __restrict__ bn_v,
    const float* __restrict__ b2)
{
    __shared__ float part[4][DCNN];
    __shared__ float s0[16];
    __shared__ float cat[80];

    int r = blockIdx.x;
    int tid = threadIdx.x;
    int pg = tid >> 6;
    int oc = tid & 63;

    float tv[9];
#pragma unroll
    for (int q = 0; q < 9; q++) tv[q] = g_t[oc * 9 + q];
    float base2 = b2[oc];

    const float* p0 = g_yp + (size_t)r * 49 * DCNN + oc;
    const size_t str = (size_t)M1 * DCNN;
    float s = 0.f;
    for (int p = pg; p < 49; p += 4) {
        int py = p / 7, px = p - py * 7;
        float v = base2;
#pragma unroll
        for (int ty = 0; ty < 3; ty++)
#pragma unroll
            for (int tx = 0; tx < 3; tx++) {
                int ny = py + ty - 1, nx = px + tx - 1;
                if ((unsigned)ny < 7u && (unsigned)nx < 7u)
                    v += tv[ty * 3 + tx];
            }
#pragma unroll
        for (int q = 0; q < KSPLIT; q++) v += p0[q * str + p * DCNN];
        s += fmaxf(v, 0.f);
    }
    part[pg][oc] = s;
    __syncthreads();

    const float* xr = x + r * 12;
    if (tid < 64) {
        float t = part[0][tid] + part[1][tid] + part[2][tid] + part[3][tid];
        float inv = bn_g[tid] * rsqrtf(bn_v[tid] + 1e-5f);
        cat[16 + tid] = (t * (1.f / 49.f) - bn_m[tid]) * inv + bn_b[tid];
    } else if (tid < 80) {
        int j = tid - 64;
        float a = a0_b[j];
#pragma unroll
        for (int q = 0; q < 12; q++) a += xr[q] * a0_w[j * 12 + q];
        s0[j] = fmaxf(a, 0.f);
    }
    __syncthreads();

    if (tid < 16) {
        float a = ai_b[tid];
#pragma unroll
        for (int j = 0; j < 16; j++) a += s0[j] * ai_w[tid * 16 + j];
        cat[tid] = s0[tid] + fmaxf(a, 0.f);
    }
    __syncthreads();

    float a = an_b[tid];
#pragma unroll
    for (int j = 0; j < 80; j++) a += cat[j] * an_w[tid * 80 + j];
    g_s[r * DRNN + tid] = fmaxf(a, 0.f);
}

// ---------------- encoder input gates: 128 blocks x 4 rows, unrolled -----
__global__ __launch_bounds__(256) void gi_kernel(const float* __restrict__ b_ih)
{
    int blk = blockIdx.x;                 // 0..127
    int d = threadIdx.x;
    __shared__ __align__(16) float svT[DRNN][4];

    for (int rr = 0; rr < 4; rr++) {
        int q = blk * 4 + rr;
        int t = q >> 5, b = q & 31;
        int r = b * 16 + t;
        svT[d][rr] = g_s[r * DRNN + d];
    }
    __syncthreads();

    float a0[4], a1[4], a2[4];
#pragma unroll
    for (int rr = 0; rr < 4; rr++) { a0[rr] = 0.f; a1[rr] = 0.f; a2[rr] = 0.f; }

    const float4* Wp = (const float4*)g_wihp;
#pragma unroll 4
    for (int kq = 0; kq < 64; kq++) {
        float4 w0 = Wp[(kq * 3 + 0) * DRNN + d];
        float4 w1 = Wp[(kq * 3 + 1) * DRNN + d];
        float4 w2 = Wp[(kq * 3 + 2) * DRNN + d];
        float w0a[4] = {w0.x, w0.y, w0.z, w0.w};
        float w1a[4] = {w1.x, w1.y, w1.z, w1.w};
        float w2a[4] = {w2.x, w2.y, w2.z, w2.w};
#pragma unroll
        for (int j = 0; j < 4; j++) {
            int k = kq * 4 + j;
            float4 sv = *(const float4*)&svT[k][0];
            float s[4] = {sv.x, sv.y, sv.z, sv.w};
#pragma unroll
            for (int u = 0; u < 4; u++) {
                a0[u] += s[u] * w0a[j];
                a1[u] += s[u] * w1a[j];
                a2[u] += s[u] * w2a[j];
            }
        }
    }

    float bi0 = b_ih[d], bi1 = b_ih[256 + d], bi2 = b_ih[512 + d];
#pragma unroll
    for (int rr = 0; rr < 4; rr++) {
        float* o = g_gi + (size_t)(blk * 4 + rr) * G3;
        o[d] = a0[rr] + bi0;
        o[256 + d] = a1[rr] + bi1;
        o[512 + d] = a2[rr] + bi2;
    }
}

__device__ __forceinline__ float sigmoidf_(float v) { return 1.f / (1.f + expf(-v)); }

// ---------------- fused encoder: 512 threads, split-K ----------------
__global__ __launch_bounds__(512) void encoder_kernel(const float* __restrict__ b_hh)
{
    int b = blockIdx.x;
    int tid = threadIdx.x;
    int half = tid >> 8;
    int d = tid & 255;
    __shared__ __align__(16) float hs[DRNN];
    __shared__ float part[3][DRNN];

    if (half == 0) hs[d] = 0.f;
    __syncthreads();

    float bh0 = b_hh[d], bh1 = b_hh[256 + d], bh2 = b_hh[512 + d];
    const float4* Wp = (const float4*)g_whhp;
    int kq0 = half * 32;

    for (int t = 0; t < LSEQ; t++) {
        float a0 = 0.f, a1 = 0.f, a2 = 0.f;
#pragma unroll 4
        for (int kq = kq0; kq < kq0 + 32; kq++) {
            float4 h4 = *(const float4*)&hs[kq * 4];
            float4 w0 = Wp[(kq * 3 + 0) * DRNN + d];
            float4 w1 = Wp[(kq * 3 + 1) * DRNN + d];
            float4 w2 = Wp[(kq * 3 + 2) * DRNN + d];
            a0 += h4.x * w0.x + h4.y * w0.y + h4.z * w0.z + h4.w * w0.w;
            a1 += h4.x * w1.x + h4.y * w1.y + h4.z * w1.z + h4.w * w1.w;
            a2 += h4.x * w2.x + h4.y * w2.y + h4.z * w2.z + h4.w * w2.w;
        }
        if (half == 1) { part[0][d] = a0; part[1][d] = a1; part[2][d] = a2; }
        float oldh = hs[d];
        __syncthreads();
        if (half == 0) {
            a0 += part[0][d] + bh0;
            a1 += part[1][d] + bh1;
            a2 += part[2][d] + bh2;
            const float* gi = g_gi + (size_t)(t * 32 + b) * G3;
            float rr = sigmoidf_(gi[d] + a0);
            float zz = sigmoidf_(gi[256 + d] + a1);
            float nn = tanhf(gi[512 + d] + rr * a2);
            hs[d] = (1.f - zz) * nn + zz * oldh;
        }
        __syncthreads();
    }
    if (half == 0) g_h[b * DRNN + d] = hs[d];
}

// ---------------- fused decoder: 512 threads, split-K ----------------
__global__ __launch_bounds__(512) void decoder_kernel(
    const float* __restrict__ b_ih, const float* __restrict__ b_hh,
    const float* __restrict__ fi_b,
    const float* __restrict__ fn_w, const float* __restrict__ fn_b,
    float* __restrict__ out)
{
    int b = blockIdx.x;
    int tid = threadIdx.x;
    int half = tid >> 8;
    int d = tid & 255;
    __shared__ __align__(16) float hs[DRNN];
    __shared__ __align__(16) float xs[DRNN];
    __shared__ float xr[DRNN];
    __shared__ float part[6][DRNN];
    __shared__ float partf[DRNN];

    if (half == 0) {
        float h0 = g_h[b * DRNN + d];
        hs[d] = h0;
        xs[d] = h0;
    }
    __syncthreads();

    float bh0 = b_hh[d], bh1 = b_hh[256 + d], bh2 = b_hh[512 + d];
    float bi0 = b_ih[d], bi1 = b_ih[256 + d], bi2 = b_ih[512 + d];
    float fib = fi_b[d];
    const float4* Wh = (const float4*)g_whhp;
    const float4* Wi = (const float4*)g_wihp;
    const float4* Wf = (const float4*)g_fitp;
    int kq0 = half * 32;

    for (int t = 0; t < HORIZON; t++) {
        float a0 = 0.f, a1 = 0.f, a2 = 0.f;
        float c0 = 0.f, c1 = 0.f, c2 = 0.f;
#pragma unroll 4
        for (int kq = kq0; kq < kq0 + 32; kq++) {
            float4 h4 = *(const float4*)&hs[kq * 4];
            float4 x4 = *(const float4*)&xs[kq * 4];
            float4 w0 = Wh[(kq * 3 + 0) * DRNN + d];
            float4 w1 = Wh[(kq * 3 + 1) * DRNN + d];
            float4 w2 = Wh[(kq * 3 + 2) * DRNN + d];
            float4 v0 = Wi[(kq * 3 + 0) * DRNN + d];
            float4 v1 = Wi[(kq * 3 + 1) * DRNN + d];
            float4 v2 = Wi[(kq * 3 + 2) * DRNN + d];
            a0 += h4.x * w0.x + h4.y * w0.y + h4.z * w0.z + h4.w * w0.w;
            a1 += h4.x * w1.x + h4.y * w1.y + h4.z * w1.z + h4.w * w1.w;
            a2 += h4.x * w2.x + h4.y * w2.y + h4.z * w2.z + h4.w * w2.w;
            c0 += x4.x * v0.x + x4.y * v0.y + x4.z * v0.z + x4.w * v0.w;
            c1 += x4.x * v1.x + x4.y * v1.y + x4.z * v1.z + x4.w * v1.w;
            c2 += x4.x * v2.x + x4.y * v2.y + x4.z * v2.z + x4.w * v2.w;
        }
        if (half == 1) {
            part[0][d] = a0; part[1][d] = a1; part[2][d] = a2;
            part[3][d] = c0; part[4][d] = c1; part[5][d] = c2;
        }
        float oldh = hs[d];
        __syncthreads();
        if (half == 0) {
            a0 += part[0][d] + bh0;
            a1 += part[1][d] + bh1;
            a2 += part[2][d] + bh2;
            c0 += part[3][d] + bi0;
            c1 += part[4][d] + bi1;
            c2 += part[5][d] + bi2;
            float rr = sigmoidf_(c0 + a0);
            float zz = sigmoidf_(c1 + a1);
            float nn = tanhf(c2 + rr * a2);
            hs[d] = (1.f - zz) * nn + zz * oldh;
        }
        __syncthreads();

        float a = 0.f;
#pragma unroll 4
        for (int kq = kq0; kq < kq0 + 32; kq++) {
            float4 h4 = *(const float4*)&hs[kq * 4];
            float4 wv = Wf[kq * DRNN + d];
            a += h4.x * wv.x + h4.y * wv.y + h4.z * wv.z + h4.w * wv.w;
        }
        if (half == 1) partf[d] = a;
        __syncthreads();
        if (half == 0) {
            a += partf[d] + fib;
            float v = hs[d] + fmaxf(a, 0.f);
            xr[d] = v;
            xs[d] = v;
        }
        __syncthreads();

        if (tid < 64) {
            int dd = tid >> 5, lane = tid & 31;
            float s = 0.f;
#pragma unroll
            for (int k = lane; k < DRNN; k += 32) s += xr[k] * fn_w[dd * DRNN + k];
#pragma unroll
            for (int o = 16; o > 0; o >>= 1)
                s += __shfl_down_sync(0xffffffffu, s, o);
            if (lane == 0)
                out[(t * 32 + b) * 2 + dd] = tanhf(s + fn_b[dd]);
        }
        __syncthreads();
    }
}

// ---------------- launch ----------------
extern "C" void kernel_launch(void* const* d_in, const int* in_sizes, int n_in,
                              void* d_out, int out_size)
{
    const float* x      = (const float*)d_in[0];
    const float* frames = (const float*)d_in[1];
    const float* cnn_w  = (const float*)d_in[2];
    const float* cnn_b  = (const float*)d_in[3];
    const float* cnn1_w = (const float*)d_in[4];
    const float* cnn1_b = (const float*)d_in[5];
    const float* bn_g   = (const float*)d_in[6];
    const float* bn_b   = (const float*)d_in[7];
    const float* bn_m   = (const float*)d_in[8];
    const float* bn_v   = (const float*)d_in[9];
    const float* a0_w   = (const float*)d_in[10];
    const float* a0_b   = (const float*)d_in[11];
    const float* ai_w   = (const float*)d_in[12];
    const float* ai_b   = (const float*)d_in[13];
    const float* an_w   = (const float*)d_in[14];
    const float* an_b   = (const float*)d_in[15];
    const float* w_ih   = (const float*)d_in[16];
    const float* w_hh   = (const float*)d_in[17];
    const float* b_ih   = (const float*)d_in[18];
    const float* b_hh   = (const float*)d_in[19];
    const float* fi_w   = (const float*)d_in[20];
    const float* fi_b   = (const float*)d_in[21];
    const float* fn_w   = (const float*)d_in[22];
    const float* fn_b   = (const float*)d_in[23];
    float* out = (float*)d_out;

    front_kernel<<<FRONTBLK, 256>>>(frames, cnn_w, cnn1_w, cnn_b,
                                    w_ih, w_hh, fi_w);

    dim3 gg(M1 / 128, KSPLIT);
    fused_gemm<<<gg, 256>>>();

    poolad_kernel<<<BL, 256>>>(x, a0_w, a0_b, ai_w, ai_b, an_w, an_b,
                               bn_g, bn_b, bn_m, bn_v, cnn1_b);
    gi_kernel<<<128, DRNN>>>(b_ih);

    encoder_kernel<<<BATCH, 512>>>(b_hh);
    decoder_kernel<<<BATCH, 512>>>(b_ih, b_hh, fi_b, fn_w, fn_b, out);
}